// round 6
// baseline (speedup 1.0000x reference)
#include <cuda_runtime.h>
#include <cuda_bf16.h>
#include <math.h>
#include <stdint.h>

// ---------------- problem constants ----------------
#define NTOK 16384   // B*T
#define CDIM 1024
#define EXP  8
#define HDIM 4096
#define K1 (3*CDIM)   // 3072
#define K2 (3*HDIM)   // 12288
#define MAXSLOT (2*NTOK)

// ---------------- device scratch ----------------
__device__ __align__(256) int   g_cnt[EXP];
__device__ __align__(256) int   g_off[EXP + 1];
__device__ __align__(256) int   g_tok[EXP * NTOK];
__device__ __align__(256) float g_prob[EXP * NTOK];
__device__ __align__(256) int   g_ta [NTOK * 8];
__device__ __align__(256) float g_tap[NTOK * 8];
__device__ __align__(256) __nv_bfloat16 g_xp [(size_t)NTOK * K1];
__device__ __align__(256) __nv_bfloat16 g_w1p[(size_t)EXP * HDIM * K1];
__device__ __align__(256) __nv_bfloat16 g_w2p[(size_t)EXP * CDIM * K2];
__device__ __align__(256) __nv_bfloat16 g_hp [(size_t)MAXSLOT * K2];
__device__ __align__(256) float g_y [(size_t)MAXSLOT * CDIM];
__device__ __align__(256) float g_h [(size_t)NTOK * HDIM];   // fp32 path scratch

// ---------------- asm helpers ----------------
__device__ __forceinline__ uint32_t smem_u32(const void* p) {
    uint32_t a;
    asm("{ .reg .u64 t; cvta.to.shared.u64 t, %1; cvt.u32.u64 %0, t; }" : "=r"(a) : "l"(p));
    return a;
}
__device__ __forceinline__ void ldsm4(uint32_t* r, uint32_t a) {
    asm volatile("ldmatrix.sync.aligned.m8n8.x4.shared.b16 {%0,%1,%2,%3}, [%4];"
                 : "=r"(r[0]), "=r"(r[1]), "=r"(r[2]), "=r"(r[3]) : "r"(a));
}
__device__ __forceinline__ void mma_bf16(float* c, const uint32_t* a, uint32_t b0, uint32_t b1) {
    asm volatile("mma.sync.aligned.m16n8k16.row.col.f32.bf16.bf16.f32 "
                 "{%0,%1,%2,%3}, {%4,%5,%6,%7}, {%8,%9}, {%0,%1,%2,%3};"
                 : "+f"(c[0]), "+f"(c[1]), "+f"(c[2]), "+f"(c[3])
                 : "r"(a[0]), "r"(a[1]), "r"(a[2]), "r"(a[3]), "r"(b0), "r"(b1));
}

// ---------------- init ----------------
__global__ void init_kernel() {
    if (threadIdx.x < EXP) g_cnt[threadIdx.x] = 0;
}
__global__ void zero_out_kernel(float* out, int n_out) {
    int i = blockIdx.x * blockDim.x + threadIdx.x;
    int stride = gridDim.x * blockDim.x;
    for (int j = i; j < n_out; j += stride) out[j] = 0.0f;
}

// ---------------- routing: 1 warp per token ----------------
__global__ void route_kernel(const float* __restrict__ x,
                             const float* __restrict__ eps,
                             const float* __restrict__ rw,
                             const float* __restrict__ rb,
                             const float* __restrict__ nw,
                             const float* __restrict__ nb,
                             const int*   __restrict__ topk_p) {
    int warp = (blockIdx.x * blockDim.x + threadIdx.x) >> 5;
    int lane = threadIdx.x & 31;
    if (warp >= NTOK) return;

    const float* xr = x + (size_t)warp * CDIM;
    float ar[EXP], an[EXP];
#pragma unroll
    for (int e = 0; e < EXP; e++) { ar[e] = 0.f; an[e] = 0.f; }
    for (int j = lane; j < CDIM; j += 32) {
        float xv = xr[j];
        const float* rwj = rw + (size_t)j * EXP;
        const float* nwj = nw + (size_t)j * EXP;
#pragma unroll
        for (int e = 0; e < EXP; e++) {
            ar[e] = fmaf(xv, rwj[e], ar[e]);
            an[e] = fmaf(xv, nwj[e], an[e]);
        }
    }
#pragma unroll
    for (int e = 0; e < EXP; e++) {
#pragma unroll
        for (int o = 16; o > 0; o >>= 1) {
            ar[e] += __shfl_xor_sync(0xffffffffu, ar[e], o);
            an[e] += __shfl_xor_sync(0xffffffffu, an[e], o);
        }
    }
    if (lane == 0) {
        int k = *topk_p; if (k > EXP) k = EXP;
        float noisy[EXP];
#pragma unroll
        for (int e = 0; e < EXP; e++) {
            float z  = an[e] + nb[e];
            float sp = (z > 20.f) ? z : log1pf(expf(z));
            noisy[e] = ar[e] + rb[e] + eps[(size_t)warp * EXP + e] * sp;
        }
        bool sel[EXP];
#pragma unroll
        for (int e = 0; e < EXP; e++) sel[e] = false;
        int idx[EXP];
        for (int t = 0; t < k; t++) {
            float best = -INFINITY; int bi = 0;
            for (int e = 0; e < EXP; e++)
                if (!sel[e] && noisy[e] > best) { best = noisy[e]; bi = e; }
            sel[bi] = true; idx[t] = bi;
        }
        float mx = -INFINITY;
        for (int t = 0; t < k; t++) mx = fmaxf(mx, noisy[idx[t]]);
        float den = 0.f;
        for (int t = 0; t < k; t++) den += expf(noisy[idx[t]] - mx);
        for (int t = 0; t < k; t++) {
            int e = idx[t];
            float p = expf(noisy[e] - mx) / den;
            int pos = atomicAdd(&g_cnt[e], 1);
            g_tok [e * NTOK + pos] = warp;
            g_prob[e * NTOK + pos] = p;
            g_ta [(warp << 3) + t] = (e << 16) | pos;
            g_tap[(warp << 3) + t] = p;
        }
    }
}

__global__ void offs_kernel() {
    if (threadIdx.x == 0) {
        int s = 0;
        for (int e = 0; e < EXP; e++) { g_off[e] = s; s += g_cnt[e]; }
        g_off[EXP] = s;
    }
}

// ---------------- conversions ----------------
__global__ void conv_x_kernel(const float* __restrict__ x) {
    int i = blockIdx.x * blockDim.x + threadIdx.x;
    int stride = gridDim.x * blockDim.x;
    for (int idx = i; idx < NTOK * CDIM; idx += stride) {
        int r = idx >> 10, k = idx & 1023;
        float v = x[idx];
        __nv_bfloat16 hi = __float2bfloat16(v);
        __nv_bfloat16 lo = __float2bfloat16(v - __bfloat162float(hi));
        __nv_bfloat16* row = g_xp + (size_t)r * K1;
        row[k] = hi; row[CDIM + k] = lo; row[2 * CDIM + k] = hi;
    }
}

__global__ void conv_w_kernel(const float* __restrict__ W, __nv_bfloat16* __restrict__ Wp,
                              int K, int N) {
    __shared__ float t[32][33];
    int e = blockIdx.z;
    const float* w = W + (size_t)e * K * N;
    __nv_bfloat16* wp = Wp + (size_t)e * N * 3 * K;
    int k0 = blockIdx.y * 32, n0 = blockIdx.x * 32;
    int tx = threadIdx.x, ty = threadIdx.y;
#pragma unroll
    for (int i = 0; i < 32; i += 8)
        t[ty + i][tx] = w[(size_t)(k0 + ty + i) * N + n0 + tx];
    __syncthreads();
#pragma unroll
    for (int i = 0; i < 32; i += 8) {
        int n = n0 + ty + i, k = k0 + tx;
        float v = t[tx][ty + i];
        __nv_bfloat16 hi = __float2bfloat16(v);
        __nv_bfloat16 lo = __float2bfloat16(v - __bfloat162float(hi));
        size_t base = (size_t)n * 3 * K;
        wp[base + k] = hi; wp[base + K + k] = hi; wp[base + 2 * K + k] = lo;
    }
}

// ---------------- HMMA grouped GEMM (under test; out gets overwritten) ----------------
#define ROWB 80

template<int MODE>
__global__ void __launch_bounds__(256)
gemm_mma(const float* __restrict__ bias) {
    constexpr int KTOT = (MODE == 0) ? K1 : K2;
    constexpr int NC = KTOT / 32;

    int e = blockIdx.z;
    int count = g_cnt[e];
    int row0 = blockIdx.y * 128;
    if (row0 >= count) return;
    int col0 = blockIdx.x * 128;

    __shared__ __align__(128) char smA[128 * ROWB];
    __shared__ __align__(128) char smB[128 * ROWB];
    __shared__ int stok[128];

    int tid = threadIdx.x;
    int lane = tid & 31, wid = tid >> 5;

    if (MODE == 0 && tid < 128) {
        int r = row0 + tid;
        stok[tid] = (r < count) ? g_tok[e * NTOK + r] : g_tok[e * NTOK];
    }
    __syncthreads();

    uint32_t smuA = smem_u32(smA);
    uint32_t smuB = smem_u32(smB);

    int lm = tid >> 1;
    int u0 = (tid & 1) * 2;
    uint32_t stO0 = (uint32_t)(lm * ROWB + u0 * 16);
    uint32_t stO1 = stO0 + 16;
    const char* aSrc;
    if (MODE == 0) {
        aSrc = (const char*)(g_xp + (size_t)stok[lm] * K1) + u0 * 16;
    } else {
        int rr = row0 + lm; if (rr >= count) rr = count - 1;
        aSrc = (const char*)(g_hp + (size_t)(g_off[e] + rr) * K2) + u0 * 16;
    }
    const __nv_bfloat16* Wb = (MODE == 0)
        ? g_w1p + (size_t)e * HDIM * K1
        : g_w2p + (size_t)e * CDIM * K2;
    const char* bSrc = (const char*)(Wb + (size_t)(col0 + lm) * KTOT) + u0 * 16;

    int warp_m = wid & 3;
    int warp_n = wid >> 2;
    int rA0 = warp_m * 32 + (lane & 15);
    uint32_t aAdr0 = smuA + (uint32_t)(rA0 * ROWB);
    uint32_t aAdr1 = aAdr0 + 16 * ROWB;
    int uAsel = lane >> 4;
    uint32_t bAdr[4];
#pragma unroll
    for (int j = 0; j < 4; j++) {
        int rB = warp_n * 64 + j * 16 + (lane & 7) + ((lane >> 4) << 3);
        bAdr[j] = smuB + (uint32_t)(rB * ROWB);
    }
    int uBsel = (lane >> 3) & 1;

    float acc[2][8][4];
#pragma unroll
    for (int i = 0; i < 2; i++)
#pragma unroll
        for (int j = 0; j < 8; j++)
#pragma unroll
            for (int r = 0; r < 4; r++) acc[i][j][r] = 0.f;

    uint4 va0, va1, vb0, vb1;
    va0 = *(const uint4*)(aSrc);
    va1 = *(const uint4*)(aSrc + 16);
    vb0 = *(const uint4*)(bSrc);
    vb1 = *(const uint4*)(bSrc + 16);

    for (int c = 0; c < NC; c++) {
        __syncthreads();
        *(uint4*)(smA + stO0) = va0;
        *(uint4*)(smA + stO1) = va1;
        *(uint4*)(smB + stO0) = vb0;
        *(uint4*)(smB + stO1) = vb1;
        __syncthreads();
        if (c + 1 < NC) {
            const char* ap = aSrc + (size_t)(c + 1) * 64;
            const char* bp = bSrc + (size_t)(c + 1) * 64;
            va0 = *(const uint4*)(ap);
            va1 = *(const uint4*)(ap + 16);
            vb0 = *(const uint4*)(bp);
            vb1 = *(const uint4*)(bp + 16);
        }
#pragma unroll
        for (int ks = 0; ks < 2; ks++) {
            uint32_t a0[4], a1[4], bq[4][4];
            uint32_t uA = (uint32_t)((ks * 2 + uAsel) * 16);
            ldsm4(a0, aAdr0 + uA);
            ldsm4(a1, aAdr1 + uA);
            uint32_t uB = (uint32_t)((ks * 2 + uBsel) * 16);
#pragma unroll
            for (int j = 0; j < 4; j++)
                ldsm4(bq[j], bAdr[j] + uB);
#pragma unroll
            for (int j = 0; j < 4; j++) {
                mma_bf16(acc[0][2 * j],     a0, bq[j][0], bq[j][1]);
                mma_bf16(acc[0][2 * j + 1], a0, bq[j][2], bq[j][3]);
                mma_bf16(acc[1][2 * j],     a1, bq[j][0], bq[j][1]);
                mma_bf16(acc[1][2 * j + 1], a1, bq[j][2], bq[j][3]);
            }
        }
    }

    int lr = lane >> 2, lc = (lane & 3) * 2;

    if (MODE == 0) {
        const float* bs = bias + (size_t)e * HDIM;
#pragma unroll
        for (int mi = 0; mi < 2; mi++) {
#pragma unroll
            for (int rp = 0; rp < 2; rp++) {
                int rt = warp_m * 32 + mi * 16 + rp * 8 + lr;
                int r = row0 + rt;
                if (r >= count) continue;
                __nv_bfloat16* hrow = g_hp + (size_t)(g_off[e] + r) * K2;
#pragma unroll
                for (int ni = 0; ni < 8; ni++) {
                    int col = col0 + warp_n * 64 + ni * 8 + lc;
                    float v0 = acc[mi][ni][rp * 2]     + bs[col];
                    float v1 = acc[mi][ni][rp * 2 + 1] + bs[col + 1];
                    v0 = v0 > 0.f ? v0 : 0.f;
                    v1 = v1 > 0.f ? v1 : 0.f;
                    __nv_bfloat16 h0 = __float2bfloat16(v0);
                    __nv_bfloat16 h1 = __float2bfloat16(v1);
                    __nv_bfloat16 l0 = __float2bfloat16(v0 - __bfloat162float(h0));
                    __nv_bfloat16 l1 = __float2bfloat16(v1 - __bfloat162float(h1));
                    __nv_bfloat162 hh; hh.x = h0; hh.y = h1;
                    __nv_bfloat162 ll; ll.x = l0; ll.y = l1;
                    *(__nv_bfloat162*)(hrow + col) = hh;
                    *(__nv_bfloat162*)(hrow + HDIM + col) = ll;
                    *(__nv_bfloat162*)(hrow + 2 * HDIM + col) = hh;
                }
            }
        }
    } else {
#pragma unroll
        for (int mi = 0; mi < 2; mi++) {
#pragma unroll
            for (int rp = 0; rp < 2; rp++) {
                int rt = warp_m * 32 + mi * 16 + rp * 8 + lr;
                int r = row0 + rt;
                if (r >= count) continue;
                float* yrow = g_y + (size_t)(g_off[e] + r) * CDIM;
#pragma unroll
                for (int ni = 0; ni < 8; ni++) {
                    int col = col0 + warp_n * 64 + ni * 8 + lc;
                    float2 v;
                    v.x = acc[mi][ni][rp * 2];
                    v.y = acc[mi][ni][rp * 2 + 1];
                    *(float2*)(yrow + col) = v;
                }
            }
        }
    }
}

// ---------------- combine (output later overwritten by fp32 path) ----------------
__global__ void combine_kernel(const float* __restrict__ b2,
                               const int* __restrict__ topk_p,
                               float* __restrict__ out) {
    int k = *topk_p; if (k > EXP) k = EXP;
    int idx = blockIdx.x * blockDim.x + threadIdx.x;
    int stride = gridDim.x * blockDim.x;
    int total = NTOK * (CDIM / 4);
    for (; idx < total; idx += stride) {
        int tok = idx >> 8;
        int c4  = (idx & 255) * 4;
        float4 acc = make_float4(0.f, 0.f, 0.f, 0.f);
        for (int t = 0; t < k; t++) {
            int meta = g_ta[(tok << 3) + t];
            float p  = g_tap[(tok << 3) + t];
            int e = meta >> 16, pos = meta & 0xffff;
            const float* yrow = g_y + (size_t)(g_off[e] + pos) * CDIM;
            const float* bb = b2 + (size_t)e * CDIM;
            float4 y = *(const float4*)(yrow + c4);
            acc.x += p * (y.x + bb[c4 + 0]);
            acc.y += p * (y.y + bb[c4 + 1]);
            acc.z += p * (y.z + bb[c4 + 2]);
            acc.w += p * (y.w + bb[c4 + 3]);
        }
        *(float4*)(out + (size_t)tok * CDIM + c4) = acc;
    }
}

// ================= R1-PROVEN fp32 path (produces the final output) =================
#define BM 128
#define BN 128
#define BKF 16
#define TM 8
#define TN 8

__global__ __launch_bounds__(256)
void gemm1_f32(const float* __restrict__ x,
               const float* __restrict__ w1,
               const float* __restrict__ b1,
               int e) {
    __shared__ float As[BKF][BM];
    __shared__ float Bs[BKF][BN];
    __shared__ int   stok[BM];

    int count = g_cnt[e];
    int row0 = blockIdx.y * BM;
    if (row0 >= count) return;
    int col0 = blockIdx.x * BN;

    int tid = threadIdx.x;
    if (tid < BM) {
        int r = row0 + tid;
        stok[tid] = (r < count) ? g_tok[e * NTOK + r] : 0;
    }
    __syncthreads();

    const float* W = w1 + (size_t)e * CDIM * HDIM;

    float acc[TM][TN];
#pragma unroll
    for (int i = 0; i < TM; i++)
#pragma unroll
        for (int j = 0; j < TN; j++) acc[i][j] = 0.f;

    int ty = tid >> 4, tx = tid & 15;
    int rbase = ty * TM, cbase = tx * TN;

    for (int k0 = 0; k0 < CDIM; k0 += BKF) {
#pragma unroll
        for (int it = 0; it < 2; it++) {
            int l = tid + it * 256;
            int m = l >> 2, kq = (l & 3) * 4;
            int t = stok[m];
            float4 v = *(const float4*)(x + (size_t)t * CDIM + k0 + kq);
            As[kq + 0][m] = v.x; As[kq + 1][m] = v.y;
            As[kq + 2][m] = v.z; As[kq + 3][m] = v.w;
        }
#pragma unroll
        for (int it = 0; it < 2; it++) {
            int l = tid + it * 256;
            int k = l >> 5, n = (l & 31) * 4;
            float4 v = *(const float4*)(W + (size_t)(k0 + k) * HDIM + col0 + n);
            *(float4*)&Bs[k][n] = v;
        }
        __syncthreads();
#pragma unroll
        for (int k = 0; k < BKF; k++) {
            float a[TM], b[TN];
            float4 a0 = *(float4*)&As[k][rbase];
            float4 a1 = *(float4*)&As[k][rbase + 4];
            a[0]=a0.x; a[1]=a0.y; a[2]=a0.z; a[3]=a0.w;
            a[4]=a1.x; a[5]=a1.y; a[6]=a1.z; a[7]=a1.w;
            float4 b0 = *(float4*)&Bs[k][cbase];
            float4 b1v = *(float4*)&Bs[k][cbase + 4];
            b[0]=b0.x; b[1]=b0.y; b[2]=b0.z; b[3]=b0.w;
            b[4]=b1v.x; b[5]=b1v.y; b[6]=b1v.z; b[7]=b1v.w;
#pragma unroll
            for (int i = 0; i < TM; i++)
#pragma unroll
                for (int j = 0; j < TN; j++)
                    acc[i][j] = fmaf(a[i], b[j], acc[i][j]);
        }
        __syncthreads();
    }

    const float* bias = b1 + (size_t)e * HDIM + col0;
#pragma unroll
    for (int i = 0; i < TM; i++) {
        int r = row0 + rbase + i;
        if (r >= count) continue;
        float* hrow = g_h + (size_t)r * HDIM + col0;
#pragma unroll
        for (int j = 0; j < TN; j++) {
            float v = acc[i][j] + bias[cbase + j];
            hrow[cbase + j] = v > 0.f ? v : 0.f;
        }
    }
}

__global__ __launch_bounds__(256)
void gemm2_f32(const float* __restrict__ w2,
               const float* __restrict__ b2,
               float* __restrict__ out,
               int e) {
    __shared__ float As[BKF][BM];
    __shared__ float Bs[BKF][BN];

    int count = g_cnt[e];
    int row0 = blockIdx.y * BM;
    if (row0 >= count) return;
    int col0 = blockIdx.x * BN;

    int tid = threadIdx.x;
    const float* W = w2 + (size_t)e * HDIM * CDIM;

    float acc[TM][TN];
#pragma unroll
    for (int i = 0; i < TM; i++)
#pragma unroll
        for (int j = 0; j < TN; j++) acc[i][j] = 0.f;

    int ty = tid >> 4, tx = tid & 15;
    int rbase = ty * TM, cbase = tx * TN;
    int rmax = count - row0;

    for (int k0 = 0; k0 < HDIM; k0 += BKF) {
#pragma unroll
        for (int it = 0; it < 2; it++) {
            int l = tid + it * 256;
            int m = l >> 2, kq = (l & 3) * 4;
            int r = (m < rmax) ? (row0 + m) : row0;
            float4 v = *(const float4*)(g_h + (size_t)r * HDIM + k0 + kq);
            As[kq + 0][m] = v.x; As[kq + 1][m] = v.y;
            As[kq + 2][m] = v.z; As[kq + 3][m] = v.w;
        }
#pragma unroll
        for (int it = 0; it < 2; it++) {
            int l = tid + it * 256;
            int k = l >> 5, n = (l & 31) * 4;
            float4 v = *(const float4*)(W + (size_t)(k0 + k) * CDIM + col0 + n);
            *(float4*)&Bs[k][n] = v;
        }
        __syncthreads();
#pragma unroll
        for (int k = 0; k < BKF; k++) {
            float a[TM], b[TN];
            float4 a0 = *(float4*)&As[k][rbase];
            float4 a1 = *(float4*)&As[k][rbase + 4];
            a[0]=a0.x; a[1]=a0.y; a[2]=a0.z; a[3]=a0.w;
            a[4]=a1.x; a[5]=a1.y; a[6]=a1.z; a[7]=a1.w;
            float4 b0 = *(float4*)&Bs[k][cbase];
            float4 b1v = *(float4*)&Bs[k][cbase + 4];
            b[0]=b0.x; b[1]=b0.y; b[2]=b0.z; b[3]=b0.w;
            b[4]=b1v.x; b[5]=b1v.y; b[6]=b1v.z; b[7]=b1v.w;
#pragma unroll
            for (int i = 0; i < TM; i++)
#pragma unroll
                for (int j = 0; j < TN; j++)
                    acc[i][j] = fmaf(a[i], b[j], acc[i][j]);
        }
        __syncthreads();
    }

    const float* bias = b2 + (size_t)e * CDIM + col0;
#pragma unroll
    for (int i = 0; i < TM; i++) {
        int r = row0 + rbase + i;
        if (r >= count) continue;
        int t = g_tok[e * NTOK + r];
        float p = g_prob[e * NTOK + r];
        float* orow = out + (size_t)t * CDIM + col0;
#pragma unroll
        for (int j = 0; j < TN; j++) {
            orow[cbase + j] += p * (acc[i][j] + bias[cbase + j]);
        }
    }
}

// ---------------- launch ----------------
extern "C" void kernel_launch(void* const* d_in, const int* in_sizes, int n_in,
                              void* d_out, int out_size) {
    const float* x    = (const float*)d_in[0];
    const float* eps  = (const float*)d_in[1];
    const float* rw   = (const float*)d_in[2];
    const float* rb   = (const float*)d_in[3];
    const float* nw   = (const float*)d_in[4];
    const float* nb   = (const float*)d_in[5];
    const float* w1   = (const float*)d_in[6];
    const float* b1   = (const float*)d_in[7];
    const float* w2   = (const float*)d_in[8];
    const float* b2   = (const float*)d_in[9];
    const int*   topk = (const int*)d_in[10];
    float* out = (float*)d_out;

    // ---- experimental bf16 HMMA pipeline (results overwritten below) ----
    init_kernel<<<1, 32>>>();
    conv_x_kernel<<<8192, 256>>>(x);
    conv_w_kernel<<<dim3(HDIM / 32, CDIM / 32, EXP), dim3(32, 8)>>>(w1, g_w1p, CDIM, HDIM);
    conv_w_kernel<<<dim3(CDIM / 32, HDIM / 32, EXP), dim3(32, 8)>>>(w2, g_w2p, HDIM, CDIM);
    route_kernel<<<(NTOK * 32) / 256, 256>>>(x, eps, rw, rb, nw, nb, topk);
    offs_kernel<<<1, 1>>>();
    gemm_mma<0><<<dim3(HDIM / 128, NTOK / 128, EXP), 256>>>(b1);
    gemm_mma<1><<<dim3(CDIM / 128, NTOK / 128, EXP), 256>>>(nullptr);
    combine_kernel<<<8192, 256>>>(b2, topk, out);

    // ---- proven fp32 path: overwrite out with the correct answer ----
    zero_out_kernel<<<1024, 256>>>(out, out_size);
    dim3 g1(HDIM / BN, NTOK / BM);
    dim3 g2(CDIM / BN, NTOK / BM);
    for (int e = 0; e < EXP; e++) {
        gemm1_f32<<<g1, 256>>>(x, w1, b1, e);
        gemm2_f32<<<g2, 256>>>(w2, b2, out, e);
    }
}